// round 14
// baseline (speedup 1.0000x reference)
#include <cuda_runtime.h>
#include <cuda_bf16.h>
#include <mma.h>
#include <math.h>
#include <stdint.h>

using namespace nvcuda;

#define NN 50000
#define NPAD 50048              // 391 * 128, padded M for unguarded wmma stores
#define EE 800000
#define NF 256
#define NH 4
#define ND 64
#define NC 16

// ---------------- device scratch (static, no allocation) ----------------
__device__ float g_feat1[NPAD * NF];    // x @ W1          [Npad,256]
__device__ float g_h[NN * NF];          // elu(aggr1+b1)   [N,256]
__device__ float g_feat2[NN * NC];      // h @ W2          [N,16]
__device__ float g_el1[NN * NH];
__device__ float g_er1[NN * NH];
__device__ float g_el2[NN];
__device__ float g_er2[NN];
__device__ int   g_deg[NN];
__device__ int   g_cur[NN];
__device__ int   g_off[NN + 1];
__device__ int   g_col[EE];             // src node per CSR slot (sorted by dst)

// bf16 split operands for tensor-core GEMM1
__device__ __nv_bfloat16 g_xh[NN * NF];
__device__ __nv_bfloat16 g_xl[NN * NF];
__device__ __nv_bfloat16 g_wh[NF * NF];   // W1^T hi  [n][k]
__device__ __nv_bfloat16 g_wl[NF * NF];   // W1^T lo  [n][k]

// ---------------- CSR build ----------------
__global__ void k_clear() {
    int i = blockIdx.x * blockDim.x + threadIdx.x;
    if (i < NN) { g_deg[i] = 0; g_cur[i] = 0; }
}

__global__ void k_hist(const int* __restrict__ dst) {
    int e = blockIdx.x * blockDim.x + threadIdx.x;
    if (e < EE) atomicAdd(&g_deg[dst[e]], 1);
}

__global__ void k_scan() {
    __shared__ int warpsum[32];
    __shared__ int carry_s;
    int t = threadIdx.x, lane = t & 31, wid = t >> 5;
    if (t == 0) carry_s = 0;
    __syncthreads();
    for (int base = 0; base < NN; base += 1024) {
        int i = base + t;
        int v = (i < NN) ? g_deg[i] : 0;
        int x = v;
        #pragma unroll
        for (int o = 1; o < 32; o <<= 1) {
            int y = __shfl_up_sync(0xffffffffu, x, o);
            if (lane >= o) x += y;
        }
        if (lane == 31) warpsum[wid] = x;
        __syncthreads();
        if (wid == 0) {
            int w = warpsum[lane];
            #pragma unroll
            for (int o = 1; o < 32; o <<= 1) {
                int y = __shfl_up_sync(0xffffffffu, w, o);
                if (lane >= o) w += y;
            }
            warpsum[lane] = w;
        }
        __syncthreads();
        int pre  = (wid > 0) ? warpsum[wid - 1] : 0;
        int incl = x + pre;
        if (i < NN) g_off[i] = carry_s + incl - v;
        int total = warpsum[31];
        __syncthreads();
        if (t == 0) carry_s += total;
        __syncthreads();
    }
    if (threadIdx.x == 0) g_off[NN] = carry_s;
}

__global__ void k_scatter(const int* __restrict__ src, const int* __restrict__ dst) {
    int e = blockIdx.x * blockDim.x + threadIdx.x;
    if (e < EE) {
        int d = dst[e];
        int p = g_off[d] + atomicAdd(&g_cur[d], 1);
        g_col[p] = src[e];
    }
}

// ---------------- bf16 split conversions ----------------
__global__ void k_cvt_x(const float* __restrict__ x) {
    int i = blockIdx.x * 256 + threadIdx.x;           // grid sized exactly NN*256/256
    float v = x[i];
    __nv_bfloat16 h = __float2bfloat16(v);
    float r = v - __bfloat162float(h);
    g_xh[i] = h;
    g_xl[i] = __float2bfloat16(r);
}

__global__ void k_cvt_w(const float* __restrict__ W1) {
    int i = blockIdx.x * 256 + threadIdx.x;           // 256 blocks -> 65536 = 256*256
    int n = i >> 8, k = i & 255;
    float v = W1[k * 256 + n];                        // transpose: W1T[n][k] = W1[k][n]
    __nv_bfloat16 h = __float2bfloat16(v);
    float r = v - __bfloat162float(h);
    g_wh[n * 256 + k] = h;
    g_wl[n * 256 + k] = __float2bfloat16(r);
}

// ---------------- GEMM1 via mma.sync (wmma bf16, split 3-term) -----------------
// feat1 = x @ W1; 2-stage cp.async pipeline; LDS=56 => conflict-free smem rows.
// Epilogue: fragments -> smem -> coalesced feat1 stores + fused el1/er1
// (BN=128 spans exactly 2 heads, so el/er are block-complete — no atomics).
#define BM 128
#define BN 128
#define BK 32
#define LDS 56
#define MAT_E (BM * LDS)                // 7168 elements per matrix tile
#define MAT_B (MAT_E * 2)               // 14336 bytes
#define STG_E (4 * MAT_E)               // 28672 elements per stage
#define STG_B (4 * MAT_B)               // 57344 bytes per stage
#define EPI_LD 132                      // epilogue smem stride (floats)
#define G1_SMEM (2 * STG_B)             // 114688 bytes (>= 128*132*4 = 67584)

__device__ __forceinline__ void cp16(uint32_t dst, const void* src, int bytes) {
    asm volatile("cp.async.cg.shared.global [%0], [%1], 16, %2;\n"
                 :: "r"(dst), "l"(src), "r"(bytes));
}

__device__ __forceinline__ void g1_fill(uint32_t sb, int tid, int m0, int n0,
                                        int stage, int kt) {
    uint32_t base = sb + stage * STG_B;
    #pragma unroll
    for (int r = 0; r < 2; r++) {
        int idx = tid + r * 256;        // 0..511
        int row = idx >> 2;             // 0..127
        int col = (idx & 3) * 8;        // 0,8,16,24
        uint32_t so = (uint32_t)(row * LDS + col) * 2;
        int gA = m0 + row;
        int ok = (gA < NN) ? 16 : 0;
        int gAc = (gA < NN) ? gA : (NN - 1);
        cp16(base + so,             g_xh + (size_t)gAc * NF + kt + col, ok);
        cp16(base + MAT_B + so,     g_xl + (size_t)gAc * NF + kt + col, ok);
        cp16(base + 2 * MAT_B + so, g_wh + (size_t)(n0 + row) * NF + kt + col, 16);
        cp16(base + 3 * MAT_B + so, g_wl + (size_t)(n0 + row) * NF + kt + col, 16);
    }
}

__global__ void __launch_bounds__(256) k_gemm1_mma(const float* __restrict__ al1,
                                                   const float* __restrict__ ar1) {
    extern __shared__ __nv_bfloat16 smem[];
    uint32_t sb = (uint32_t)__cvta_generic_to_shared(smem);
    const int tid = threadIdx.x;
    const int warp = tid >> 5;
    const int wm = warp & 3;                    // 4 warps along M (32 rows each)
    const int wn = warp >> 2;                   // 2 warps along N (64 cols each)
    const int m0 = blockIdx.y * BM;
    const int n0 = blockIdx.x * BN;

    wmma::fragment<wmma::accumulator, 16, 16, 16, float> acc[2][4];
    #pragma unroll
    for (int i = 0; i < 2; i++)
        #pragma unroll
        for (int j = 0; j < 4; j++) wmma::fill_fragment(acc[i][j], 0.0f);

    g1_fill(sb, tid, m0, n0, 0, 0);
    asm volatile("cp.async.commit_group;\n");

    #pragma unroll 1
    for (int kt = 0; kt < NF / BK; kt++) {
        if (kt + 1 < NF / BK) {
            g1_fill(sb, tid, m0, n0, (kt + 1) & 1, (kt + 1) * BK);
            asm volatile("cp.async.commit_group;\n");
            asm volatile("cp.async.wait_group 1;\n");
        } else {
            asm volatile("cp.async.wait_group 0;\n");
        }
        __syncthreads();

        const __nv_bfloat16* st = smem + (kt & 1) * STG_E;
        #pragma unroll
        for (int kk = 0; kk < BK; kk += 16) {
            wmma::fragment<wmma::matrix_a, 16, 16, 16, __nv_bfloat16, wmma::row_major> ah[2], al[2];
            wmma::fragment<wmma::matrix_b, 16, 16, 16, __nv_bfloat16, wmma::col_major> bh[4], bl[4];
            #pragma unroll
            for (int i = 0; i < 2; i++) {
                const __nv_bfloat16* p = st + (wm * 32 + i * 16) * LDS + kk;
                wmma::load_matrix_sync(ah[i], p, LDS);
                wmma::load_matrix_sync(al[i], p + MAT_E, LDS);
            }
            #pragma unroll
            for (int j = 0; j < 4; j++) {
                const __nv_bfloat16* p = st + 2 * MAT_E + (wn * 64 + j * 16) * LDS + kk;
                wmma::load_matrix_sync(bh[j], p, LDS);
                wmma::load_matrix_sync(bl[j], p + MAT_E, LDS);
            }
            #pragma unroll
            for (int i = 0; i < 2; i++)
                #pragma unroll
                for (int j = 0; j < 4; j++) {
                    wmma::mma_sync(acc[i][j], ah[i], bh[j], acc[i][j]);
                    wmma::mma_sync(acc[i][j], ah[i], bl[j], acc[i][j]);
                    wmma::mma_sync(acc[i][j], al[i], bh[j], acc[i][j]);
                }
        }
        __syncthreads();
    }

    // ---- epilogue: fragments -> smem, then coalesced stores + fused el/er ----
    float* sd = (float*)smem;                   // 128 x EPI_LD fp32 tile
    #pragma unroll
    for (int i = 0; i < 2; i++)
        #pragma unroll
        for (int j = 0; j < 4; j++)
            wmma::store_matrix_sync(sd + (wm * 32 + i * 16) * EPI_LD + wn * 64 + j * 16,
                                    acc[i][j], EPI_LD, wmma::mem_row_major);
    __syncthreads();

    // coalesced feat1 write: 4096 float4s; warp covers one full 512B row
    #pragma unroll
    for (int r = 0; r < 16; r++) {
        int idx = tid + r * 256;
        int row = idx >> 5, c4 = (idx & 31) * 4;
        float4 v = *(const float4*)(sd + row * EPI_LD + c4);
        *(float4*)(g_feat1 + (size_t)(m0 + row) * NF + n0 + c4) = v;
    }

    // fused el/er: thread t -> row t>>1, head segment t&1 (block spans 2 heads)
    {
        int row = tid >> 1, s = tid & 1;
        int head = (n0 >> 6) + s;
        if (m0 + row < NN) {
            const float4* f = (const float4*)(sd + row * EPI_LD + s * 64);
            const float4* a = (const float4*)(al1 + head * 64);
            const float4* r = (const float4*)(ar1 + head * 64);
            float sl = 0.f, sr = 0.f;
            #pragma unroll
            for (int i = 0; i < 16; i++) {
                float4 v = f[i], A = a[i], R = r[i];
                sl += v.x * A.x + v.y * A.y + v.z * A.z + v.w * A.w;
                sr += v.x * R.x + v.y * R.y + v.z * R.z + v.w * R.w;
            }
            g_el1[(m0 + row) * 4 + head] = sl;
            g_er1[(m0 + row) * 4 + head] = sr;
        }
    }
}

// ---------------- layer-1 fused softmax-aggregate (single pass, float4, 64 thr/node)
__global__ void __launch_bounds__(64) k_aggr1(const float* __restrict__ b1) {
    int n = blockIdx.x;
    int t = threadIdx.x;                 // 0..63
    int beg = g_off[n], deg = g_off[n + 1] - beg;

    __shared__ float s_ex[64][5];        // stride 5: conflict-free writes
    __shared__ int   s_src[64];

    float4 bb = ((const float4*)b1)[t];

    if (deg == 0) {
        float4 o;
        o.x = bb.x > 0.f ? bb.x : __expf(bb.x) - 1.f;
        o.y = bb.y > 0.f ? bb.y : __expf(bb.y) - 1.f;
        o.z = bb.z > 0.f ? bb.z : __expf(bb.z) - 1.f;
        o.w = bb.w > 0.f ? bb.w : __expf(bb.w) - 1.f;
        ((float4*)(g_h + n * 256))[t] = o;
        return;
    }

    float4 ern = *(const float4*)(g_er1 + n * 4);
    const int h = t >> 4;                // head for this thread's slot

    float4 acc = make_float4(0.f, 0.f, 0.f, 0.f);
    float den = 0.f;

    for (int base = 0; base < deg; base += 64) {
        int i = base + t;
        if (i < deg) {
            int s = g_col[beg + i];
            s_src[t] = s;
            float4 el = *(const float4*)(g_el1 + s * 4);
            float e0 = el.x + ern.x; e0 = e0 > 0.f ? e0 : 0.2f * e0;
            float e1 = el.y + ern.y; e1 = e1 > 0.f ? e1 : 0.2f * e1;
            float e2 = el.z + ern.z; e2 = e2 > 0.f ? e2 : 0.2f * e2;
            float e3 = el.w + ern.w; e3 = e3 > 0.f ? e3 : 0.2f * e3;
            s_ex[t][0] = __expf(e0);
            s_ex[t][1] = __expf(e1);
            s_ex[t][2] = __expf(e2);
            s_ex[t][3] = __expf(e3);
        }
        __syncthreads();
        int cnt = min(64, deg - base);
        #pragma unroll 8
        for (int j = 0; j < cnt; j++) {
            const float4* row = (const float4*)(g_feat1 + (size_t)s_src[j] * 256);
            float a = s_ex[j][h];
            float4 v = row[t];
            den   += a;
            acc.x += v.x * a;
            acc.y += v.y * a;
            acc.z += v.z * a;
            acc.w += v.w * a;
        }
        __syncthreads();
    }
    float inv = 1.f / den;
    float4 o;
    o.x = acc.x * inv + bb.x; o.x = o.x > 0.f ? o.x : __expf(o.x) - 1.f;
    o.y = acc.y * inv + bb.y; o.y = o.y > 0.f ? o.y : __expf(o.y) - 1.f;
    o.z = acc.z * inv + bb.z; o.z = o.z > 0.f ? o.z : __expf(o.z) - 1.f;
    o.w = acc.w * inv + bb.w; o.w = o.w > 0.f ? o.w : __expf(o.w) - 1.f;
    ((float4*)(g_h + n * 256))[t] = o;
}

// ---------------- GEMM2 (h @ W2) fused with el2/er2 reduction ----------------
__global__ void __launch_bounds__(256) k_gemm2(const float* __restrict__ W2,
                                               const float* __restrict__ al2,
                                               const float* __restrict__ ar2) {
    __shared__ float Ws[4096];
    __shared__ float Hs[4096];
    int tid = threadIdx.x;
    int nb0 = blockIdx.x * 16;

    const float4* w4 = (const float4*)W2;
    float4* ws4 = (float4*)Ws;
    const float4* h4 = (const float4*)(g_h + nb0 * 256);
    float4* hs4 = (float4*)Hs;
    for (int i = tid; i < 1024; i += 256) { ws4[i] = w4[i]; hs4[i] = h4[i]; }
    __syncthreads();

    int r = tid >> 4, c = tid & 15;
    const float* hr = Hs + r * 256;
    float acc = 0.f;
    #pragma unroll 8
    for (int k = 0; k < 256; k++) acc += hr[k] * Ws[k * 16 + c];

    int node = nb0 + r;
    g_feat2[node * 16 + c] = acc;

    float vl = acc * al2[c];
    float vr = acc * ar2[c];
    #pragma unroll
    for (int o = 8; o; o >>= 1) {
        vl += __shfl_xor_sync(0xffffffffu, vl, o);
        vr += __shfl_xor_sync(0xffffffffu, vr, o);
    }
    if (c == 0) { g_el2[node] = vl; g_er2[node] = vr; }
}

// ---------------- layer-2 softmax-aggregate + bias + log_softmax (warp/node) ------
__global__ void __launch_bounds__(256) k_aggr2(const float* __restrict__ b2,
                                               float* __restrict__ out) {
    int n = (blockIdx.x * blockDim.x + threadIdx.x) >> 5;
    int lane = threadIdx.x & 31;
    if (n >= NN) return;
    int beg = g_off[n], deg = g_off[n + 1] - beg;

    float v;
    if (deg == 0) {
        v = b2[lane & 15];
    } else {
        float ern = g_er2[n];
        int f = lane & 15, half = lane >> 4;
        float acc = 0.f, den = 0.f;
        for (int i = half; i < deg; i += 2) {
            int s = g_col[beg + i];
            float e = g_el2[s] + ern; e = e > 0.f ? e : 0.2f * e;
            float a = __expf(e);
            den += a;
            acc += g_feat2[s * 16 + f] * a;
        }
        acc += __shfl_xor_sync(0xffffffffu, acc, 16);
        den += __shfl_xor_sync(0xffffffffu, den, 16);
        v = acc / den + b2[lane & 15];
    }
    // fused log_softmax over the 16 classes (one per lane in each half-warp)
    float m = v;
    #pragma unroll
    for (int o = 8; o; o >>= 1) m = fmaxf(m, __shfl_xor_sync(0xffffffffu, m, o));
    float s = expf(v - m);
    #pragma unroll
    for (int o = 8; o; o >>= 1) s += __shfl_xor_sync(0xffffffffu, s, o);
    if (lane < 16) out[n * 16 + lane] = v - (m + logf(s));
}

// ---------------- launch ----------------
extern "C" void kernel_launch(void* const* d_in, const int* in_sizes, int n_in,
                              void* d_out, int out_size) {
    const float* x   = (const float*)d_in[0];
    const int*   src = (const int*)d_in[1];
    const int*   dst = (const int*)d_in[2];
    const float* W1  = (const float*)d_in[3];
    const float* al1 = (const float*)d_in[4];
    const float* ar1 = (const float*)d_in[5];
    const float* b1  = (const float*)d_in[6];
    const float* W2  = (const float*)d_in[7];
    const float* al2 = (const float*)d_in[8];
    const float* ar2 = (const float*)d_in[9];
    const float* b2  = (const float*)d_in[10];
    float* out = (float*)d_out;

    static cudaStream_t s2 = nullptr;
    static cudaEvent_t evFork = nullptr, evJoin = nullptr;
    if (!s2) {
        cudaFuncSetAttribute(k_gemm1_mma, cudaFuncAttributeMaxDynamicSharedMemorySize, G1_SMEM);
        cudaStreamCreateWithFlags(&s2, cudaStreamNonBlocking);
        cudaEventCreateWithFlags(&evFork, cudaEventDisableTiming);
        cudaEventCreateWithFlags(&evJoin, cudaEventDisableTiming);
    }

    // fork: CSR build chain on s2, dense chain on the main stream
    cudaEventRecord(evFork, 0);
    cudaStreamWaitEvent(s2, evFork, 0);

    k_clear<<<(NN + 255) / 256, 256, 0, s2>>>();
    k_hist<<<(EE + 255) / 256, 256, 0, s2>>>(dst);
    k_scan<<<1, 1024, 0, s2>>>();
    k_scatter<<<(EE + 255) / 256, 256, 0, s2>>>(src, dst);
    cudaEventRecord(evJoin, s2);

    // dense chain (independent of CSR); el1/er1 fused into gemm1 epilogue
    k_cvt_x<<<(NN * NF) / 256, 256>>>(x);
    k_cvt_w<<<(NF * NF) / 256, 256>>>(W1);
    k_gemm1_mma<<<dim3(NF / BN, NPAD / BM), 256, G1_SMEM>>>(al1, ar1);

    // join: aggregation needs both CSR and feat1/el1
    cudaStreamWaitEvent(0, evJoin, 0);

    k_aggr1<<<NN, 64>>>(b1);
    k_gemm2<<<NN / 16, 256>>>(W2, al2, ar2);
    k_aggr2<<<(NN * 32 + 255) / 256, 256>>>(b2, out);
}